// round 8
// baseline (speedup 1.0000x reference)
#include <cuda_runtime.h>
#include <math.h>

// Problem constants
#define BB   4
#define NN1  16384
#define NN2  4096
#define CC   128
#define KIN  384      // 3*C
#define MOUT 256      // MLP width (both layers)
#define TN   64       // points per block tile in main kernel
#define SX   66       // padded smem row stride (floats): even -> 8B-aligned rows for f32x2

typedef unsigned long long ull;

// ---------------- f32x2 packed helpers (sm_103a) --------------------------
__device__ __forceinline__ void ffma2(ull& d, ull a, ull b) {
    asm("fma.rn.f32x2 %0, %1, %2, %3;" : "=l"(d) : "l"(a), "l"(b), "l"(d));
}
__device__ __forceinline__ ull pack2(float lo, float hi) {
    ull r; asm("mov.b64 %0, {%1, %2};" : "=l"(r) : "f"(lo), "f"(hi)); return r;
}
__device__ __forceinline__ void unpack2(float& lo, float& hi, ull v) {
    asm("mov.b64 {%0, %1}, %2;" : "=f"(lo), "=f"(hi) : "l"(v));
}

// ---------------- device scratch (no allocations allowed) ----------------
__device__ float g_w0f[MOUT * KIN];    // BN-folded weights layer 0
__device__ float g_b0f[MOUT];
__device__ float g_w1f[MOUT * MOUT];   // BN-folded weights layer 1
__device__ float g_b1f[MOUT];
__device__ float g_p2t[BB * NN2 * CC]; // transposed points2: (B, N2, C)
__device__ int   g_i3[BB * NN1 * 3];   // 3-NN indices
__device__ float g_wt3[BB * NN1 * 3];  // normalized inverse-distance weights

// ---------------- BN fold: w' = w * g*rsqrt(v+eps), b' = (b-m)*s + beta ---
__global__ void fold_kernel(const float* __restrict__ w, const float* __restrict__ b,
                            const float* __restrict__ g, const float* __restrict__ beta,
                            const float* __restrict__ m, const float* __restrict__ v,
                            int layer)
{
    const int K = (layer == 0) ? KIN : MOUT;
    float* wf = (layer == 0) ? g_w0f : g_w1f;
    float* bf = (layer == 0) ? g_b0f : g_b1f;
    int idx = blockIdx.x * blockDim.x + threadIdx.x;
    if (idx < MOUT * K) {
        int o = idx / K;
        float s = g[o] * rsqrtf(v[o] + 1e-5f);
        wf[idx] = w[idx] * s;
    }
    if (idx < MOUT) {
        float s = g[idx] * rsqrtf(v[idx] + 1e-5f);
        bf[idx] = (b[idx] - m[idx]) * s + beta[idx];
    }
}

// ---------------- transpose points2 (B,C,N2) -> (B,N2,C) ------------------
__global__ void transpose_kernel(const float* __restrict__ p2)
{
    __shared__ float tile[32][33];
    int b  = blockIdx.z;
    int n0 = blockIdx.x * 32;
    int c0 = blockIdx.y * 32;
    int tx = threadIdx.x, ty = threadIdx.y;   // block (32, 8)
    #pragma unroll
    for (int r = 0; r < 32; r += 8)
        tile[ty + r][tx] = p2[(b * CC + c0 + ty + r) * NN2 + n0 + tx];
    __syncthreads();
    #pragma unroll
    for (int r = 0; r < 32; r += 8)
        g_p2t[(b * NN2 + n0 + ty + r) * CC + c0 + tx] = tile[tx][ty + r];
}

// ---------------- 3-NN search: 4 query points per thread ------------------
// score = 2*q.dot(p) - |p|^2 ; argmax score == argmin squared distance.
// d = |q|^2 - score reproduces the reference's GEMM-form distance.
// Strict '>' keeps earliest index on ties (matches top_k).
// 128 threads x 4 pts = 512 pts/block; 128 blocks -> one full wave, and each
// LDS.128 of the candidate table is amortized over 4 points (4x less smem BW).
__global__ void __launch_bounds__(128, 1)
nn3_kernel(const float* __restrict__ xyz1, const float* __restrict__ xyz2)
{
    extern __shared__ float4 sc[];   // NN2 float4 = 64KB
    const int tid  = threadIdx.x;
    const int base = blockIdx.x * 512;
    const int b    = base >> 14;     // 512 | 16384, so whole block in one batch
    const float* x2 = xyz2 + b * NN2 * 3;
    for (int j = tid; j < NN2; j += 128) {
        float x = x2[j * 3], y = x2[j * 3 + 1], z = x2[j * 3 + 2];
        sc[j] = make_float4(x, y, z, -(x * x + y * y + z * z));
    }
    __syncthreads();

    float qx[4], qy[4], qz[4], xx[4];
    float s0[4], s1[4], s2[4];
    int   j0[4], j1[4], j2[4];
    #pragma unroll
    for (int k = 0; k < 4; k++) {
        int pt = base + tid + 128 * k;
        float px = xyz1[pt * 3], py = xyz1[pt * 3 + 1], pz = xyz1[pt * 3 + 2];
        xx[k] = px * px + py * py + pz * pz;
        qx[k] = px + px; qy[k] = py + py; qz[k] = pz + pz;
        s0[k] = s1[k] = s2[k] = -INFINITY;
        j0[k] = j1[k] = j2[k] = 0;
    }

    #pragma unroll 2
    for (int j = 0; j < NN2; j++) {
        float4 f = sc[j];
        #pragma unroll
        for (int k = 0; k < 4; k++) {
            float sco = fmaf(qx[k], f.x, fmaf(qy[k], f.y, fmaf(qz[k], f.z, f.w)));
            if (sco > s2[k]) {
                if (sco > s1[k]) {
                    s2[k] = s1[k]; j2[k] = j1[k];
                    if (sco > s0[k]) { s1[k] = s0[k]; j1[k] = j0[k]; s0[k] = sco; j0[k] = j; }
                    else             { s1[k] = sco; j1[k] = j; }
                } else { s2[k] = sco; j2[k] = j; }
            }
        }
    }

    #pragma unroll
    for (int k = 0; k < 4; k++) {
        int pt = base + tid + 128 * k;
        float d0 = xx[k] - s0[k], d1 = xx[k] - s1[k], d2 = xx[k] - s2[k];
        float w0 = 1.0f / d0, w1 = 1.0f / d1, w2 = 1.0f / d2;
        float inv = 1.0f / (w0 + w1 + w2);
        g_i3 [pt * 3 + 0] = j0[k]; g_i3 [pt * 3 + 1] = j1[k]; g_i3 [pt * 3 + 2] = j2[k];
        g_wt3[pt * 3 + 0] = w0 * inv;
        g_wt3[pt * 3 + 1] = w1 * inv;
        g_wt3[pt * 3 + 2] = w2 * inv;
    }
}

// ---------------- tiled GEMM (packed f32x2) on one 256 x 64 tile ----------
// W: (256, K) row-major global; x: smem [K][SX]; double-buffered 16-row
// weight stages; each thread owns an 8x8 micro-tile held as 8x4 f32x2 pairs.
template <int K>
__device__ __forceinline__ void gemm_tile(const float* __restrict__ Wg,
                                          const float* __restrict__ xsrc,
                                          float* __restrict__ ws,
                                          ull (&acc2)[8][4],
                                          int tid, int ty, int tx)
{
    const float* wrow = Wg + tid * K;   // thread tid stages output row m = tid
    float4 pf[4];
    #pragma unroll
    for (int q = 0; q < 4; q++)
        pf[q] = *reinterpret_cast<const float4*>(wrow + 4 * q);
    #pragma unroll
    for (int q = 0; q < 4; q++) {
        ws[(4 * q + 0) * 256 + tid] = pf[q].x;
        ws[(4 * q + 1) * 256 + tid] = pf[q].y;
        ws[(4 * q + 2) * 256 + tid] = pf[q].z;
        ws[(4 * q + 3) * 256 + tid] = pf[q].w;
    }
    __syncthreads();

    #pragma unroll 1
    for (int kc = 0; kc < K; kc += 16) {
        const float* wbuf = ws + ((kc >> 4) & 1) * 4096;
        const bool more = (kc + 16) < K;
        if (more) {
            #pragma unroll
            for (int q = 0; q < 4; q++)
                pf[q] = *reinterpret_cast<const float4*>(wrow + kc + 16 + 4 * q);
        }
        #pragma unroll 4
        for (int s = 0; s < 16; s++) {
            const float* xrow = xsrc + (kc + s) * SX + tx * 8;   // 8B aligned (SX even)
            const float* wsr  = wbuf + s * 256 + ty * 8;
            ull xr2[4], wr2[8];
            #pragma unroll
            for (int j = 0; j < 4; j++)
                xr2[j] = *reinterpret_cast<const ull*>(xrow + 2 * j);
            #pragma unroll
            for (int i = 0; i < 8; i++) {
                float w = wsr[i];
                wr2[i] = pack2(w, w);
            }
            #pragma unroll
            for (int i = 0; i < 8; i++)
                #pragma unroll
                for (int j = 0; j < 4; j++)
                    ffma2(acc2[i][j], wr2[i], xr2[j]);
        }
        if (more) {
            float* nbuf = ws + (((kc >> 4) + 1) & 1) * 4096;
            #pragma unroll
            for (int q = 0; q < 4; q++) {
                nbuf[(4 * q + 0) * 256 + tid] = pf[q].x;
                nbuf[(4 * q + 1) * 256 + tid] = pf[q].y;
                nbuf[(4 * q + 2) * 256 + tid] = pf[q].z;
                nbuf[(4 * q + 3) * 256 + tid] = pf[q].w;
            }
        }
        __syncthreads();
    }
}

// ---------------- fused: interp-gather + concat + MLP x2 + channel max ----
__global__ void __launch_bounds__(256, 1)
fp_main_kernel(const float* __restrict__ points1,
               const float* __restrict__ pointsb1,
               float* __restrict__ out)
{
    extern __shared__ float smem[];
    float* xs = smem;                       // KIN * SX floats
    float* ws = smem + KIN * SX;            // 8192 floats (2 stages x 16 x 256)
    float* pm = ws + 8192;                  // 32 * TN floats

    const int tid = threadIdx.x;
    const int ty = tid >> 3, tx = tid & 7;
    const int blk = blockIdx.x;
    const int b = blk >> 8;                 // 256 tiles per batch
    const int n1base = (blk & 255) * TN;

    // --- build x tile: rows 0..127 points1, 128..255 fused, 256..383 points_b1
    const float* p1 = points1  + (b * CC) * NN1 + n1base;
    const float* pb = pointsb1 + (b * CC) * NN1 + n1base;
    for (int i = tid; i < CC * TN; i += 256) {
        int c = i >> 6, n = i & 63;
        xs[c * SX + n]          = p1[c * NN1 + n];
        xs[(256 + c) * SX + n]  = pb[c * NN1 + n];
    }
    {
        int warp = tid >> 5, lane = tid & 31;
        const float* p2b = g_p2t + b * NN2 * CC;
        #pragma unroll 1
        for (int j = 0; j < 8; j++) {
            int n  = warp * 8 + j;
            int pt = b * NN1 + n1base + n;
            int i0 = g_i3[pt * 3], i1 = g_i3[pt * 3 + 1], i2 = g_i3[pt * 3 + 2];
            float w0 = g_wt3[pt * 3], w1 = g_wt3[pt * 3 + 1], w2 = g_wt3[pt * 3 + 2];
            const float* r0 = p2b + i0 * CC;
            const float* r1 = p2b + i1 * CC;
            const float* r2 = p2b + i2 * CC;
            #pragma unroll
            for (int t = 0; t < 4; t++) {
                int c = lane + 32 * t;
                float v = w0 * r0[c] + w1 * r1[c] + w2 * r2[c];
                xs[(128 + c) * SX + n] = v;   // 2-way conflict at SX=66: negligible
            }
        }
    }
    __syncthreads();

    ull acc2[8][4];
    #pragma unroll
    for (int i = 0; i < 8; i++)
        #pragma unroll
        for (int j = 0; j < 4; j++) acc2[i][j] = 0ull;

    // layer 0: y1 = relu(W0f @ x + b0f)
    gemm_tile<KIN>(g_w0f, xs, ws, acc2, tid, ty, tx);

    #pragma unroll
    for (int i = 0; i < 8; i++) {
        float bb = g_b0f[ty * 8 + i];
        float* xrw = xs + (ty * 8 + i) * SX + tx * 8;
        #pragma unroll
        for (int j = 0; j < 4; j++) {
            float lo, hi;
            unpack2(lo, hi, acc2[i][j]);
            xrw[2 * j]     = fmaxf(lo + bb, 0.0f);
            xrw[2 * j + 1] = fmaxf(hi + bb, 0.0f);
            acc2[i][j] = 0ull;
        }
    }
    __syncthreads();

    // layer 1: y2 = relu(W1f @ y1 + b1f); relu folded into the final max
    gemm_tile<MOUT>(g_w1f, xs, ws, acc2, tid, ty, tx);

    #pragma unroll
    for (int j = 0; j < 4; j++) {
        float mlo = -INFINITY, mhi = -INFINITY;
        #pragma unroll
        for (int i = 0; i < 8; i++) {
            float bb = g_b1f[ty * 8 + i];
            float lo, hi;
            unpack2(lo, hi, acc2[i][j]);
            mlo = fmaxf(mlo, lo + bb);
            mhi = fmaxf(mhi, hi + bb);
        }
        pm[ty * TN + tx * 8 + 2 * j]     = mlo;
        pm[ty * TN + tx * 8 + 2 * j + 1] = mhi;
    }
    __syncthreads();

    if (tid < TN) {
        float mv = 0.0f;   // relu floor
        #pragma unroll
        for (int t = 0; t < 32; t++)
            mv = fmaxf(mv, pm[t * TN + tid]);
        out[b * NN1 + n1base + tid] = mv;
    }
}

// ---------------- launch --------------------------------------------------
extern "C" void kernel_launch(void* const* d_in, const int* in_sizes, int n_in,
                              void* d_out, int out_size)
{
    const float* xyz1     = (const float*)d_in[0];
    const float* xyz2     = (const float*)d_in[1];
    const float* points2  = (const float*)d_in[2];
    const float* points1  = (const float*)d_in[3];
    const float* pointsb1 = (const float*)d_in[4];
    const float* w0 = (const float*)d_in[5];
    const float* b0 = (const float*)d_in[6];
    const float* g0 = (const float*)d_in[7];
    const float* be0 = (const float*)d_in[8];
    const float* m0 = (const float*)d_in[9];
    const float* v0 = (const float*)d_in[10];
    const float* w1 = (const float*)d_in[11];
    const float* b1 = (const float*)d_in[12];
    const float* g1 = (const float*)d_in[13];
    const float* be1 = (const float*)d_in[14];
    const float* m1 = (const float*)d_in[15];
    const float* v1 = (const float*)d_in[16];
    float* out = (float*)d_out;

    const int smem_nn   = NN2 * 16;                        // 64 KB
    const int smem_main = (KIN * SX + 8192 + 32 * TN) * 4; // 142336 B
    cudaFuncSetAttribute(nn3_kernel, cudaFuncAttributeMaxDynamicSharedMemorySize, smem_nn);
    cudaFuncSetAttribute(fp_main_kernel, cudaFuncAttributeMaxDynamicSharedMemorySize, smem_main);

    fold_kernel<<<(MOUT * KIN + 255) / 256, 256>>>(w0, b0, g0, be0, m0, v0, 0);
    fold_kernel<<<(MOUT * MOUT + 255) / 256, 256>>>(w1, b1, g1, be1, m1, v1, 1);
    transpose_kernel<<<dim3(NN2 / 32, CC / 32, BB), dim3(32, 8)>>>(points2);
    nn3_kernel<<<(BB * NN1) / 512, 128, smem_nn>>>(xyz1, xyz2);
    fp_main_kernel<<<BB * (NN1 / TN), 256, smem_main>>>(points1, pointsb1, out);
}